// round 15
// baseline (speedup 1.0000x reference)
#include <cuda_runtime.h>
#include <cuda_bf16.h>
#include <cstdint>
#include <math.h>

#define N_  4096
#define D_  64
#define T_  60
#define H_  128
#define G_  512
#define NT_ 245760
#define KCAT 192
#define NKT 12
#define ASTR 200
#define WFRAGN (64*NKT*32)

// B columns permuted so tile 2p holds (i,f), tile 2p+1 holds (g,o) of the same
// channels -> cell update is fully thread-local (no shfl).
// LSTM: row-partitioned persistent kernel; input GEMM fused via concatenated K.

__device__ float g_xT[(size_t)T_*N_*D_];
__device__ float g_h[N_*H_];
__device__ float g_hb[N_*H_];
__device__ float g_WpT[D_*G_];               // plain layout: [d][g], g=gate*128+ch
__device__ float g_biasP[G_];                // plain: bias[gate*128+ch]
__device__ uint2 g_WfragHi[WFRAGN];          // [jt][kt][lane]
__device__ uint2 g_WfragLo2[WFRAGN];         // [w][kt][lane][nt]
__device__ float g_bn1sum[D_], g_bn1sq[D_];
__device__ float g_bn2sum[H_], g_bn2sq[H_];
__device__ float g_wa1[H_], g_wa2[H_], g_cc[2];
__device__ float g_s1[N_], g_s2[N_];
__device__ float g_s1s[N_];
__device__ int   g_perm[N_];
__device__ float g_e1[N_], g_e2[N_];
__device__ double g_P1[(size_t)(N_+1)*H_];
__device__ double g_P2[(size_t)(N_+1)*H_];
__device__ double g_D1[N_+1], g_D2[N_+1];
__device__ float g_M;

__device__ __forceinline__ float sigmoidf_(float v) { return 1.f/(1.f + expf(-v)); }
__device__ __forceinline__ float fsig(float x) { return 1.f/(1.f + __expf(-x)); }
__device__ __forceinline__ float ftanh(float x) {
    float e = __expf(-2.f*fabsf(x));
    float r = (1.f - e)/(1.f + e);
    return x < 0.f ? -r : r;
}
__device__ __forceinline__ uint32_t smem_u32(const void* p) {
    uint32_t a;
    asm("{ .reg .u64 t; cvta.to.shared.u64 t, %1; cvt.u32.u64 %0, t; }" : "=r"(a) : "l"(p));
    return a;
}
__device__ __forceinline__ void ldsm_x4(uint32_t* r, uint32_t a) {
    asm volatile("ldmatrix.sync.aligned.m8n8.x4.shared.b16 {%0,%1,%2,%3}, [%4];"
        : "=r"(r[0]), "=r"(r[1]), "=r"(r[2]), "=r"(r[3]) : "r"(a));
}
__device__ __forceinline__ void mma_bf16(float* d, const uint32_t* a, const uint32_t* b) {
    asm volatile("mma.sync.aligned.m16n8k16.row.col.f32.bf16.bf16.f32 "
        "{%0,%1,%2,%3}, {%4,%5,%6,%7}, {%8,%9}, {%0,%1,%2,%3};"
        : "+f"(d[0]), "+f"(d[1]), "+f"(d[2]), "+f"(d[3])
        : "r"(a[0]), "r"(a[1]), "r"(a[2]), "r"(a[3]), "r"(b[0]), "r"(b[1]));
}
__device__ __forceinline__ uint32_t pack2bf(float a, float b) {
    __nv_bfloat16 ha = __float2bfloat16(a), hb = __float2bfloat16(b);
    return (uint32_t)__bfloat16_as_ushort(ha) | ((uint32_t)__bfloat16_as_ushort(hb) << 16);
}

__global__ void k_init() {
    int idx = blockIdx.x*blockDim.x + threadIdx.x;
    if (idx < D_) { g_bn1sum[idx] = 0.f; g_bn1sq[idx] = 0.f; }
    if (idx < H_) { g_bn2sum[idx] = 0.f; g_bn2sq[idx] = 0.f; }
}

// Transpose x + BN1 stats (single pass)
__global__ void k_xt(const float* __restrict__ x) {
    __shared__ float tile[D_*T_];
    int n = blockIdx.x;
    const float* xp = x + (size_t)n*D_*T_;
    for (int i = threadIdx.x; i < D_*T_; i += 256) tile[i] = xp[i];
    __syncthreads();
    for (int i = threadIdx.x; i < D_*T_; i += 256) {
        int t = i >> 6, d = i & 63;
        g_xT[(size_t)t*N_*D_ + (size_t)n*D_ + d] = tile[d*T_ + t];
    }
    if (threadIdx.x < D_) {
        float s = 0.f, q = 0.f;
        const float* row = tile + threadIdx.x*T_;
        #pragma unroll
        for (int t = 0; t < T_; ++t) { float v = row[t]; s += v; q += v*v; }
        atomicAdd(&g_bn1sum[threadIdx.x], s);
        atomicAdd(&g_bn1sq[threadIdx.x],  q);
    }
}

__global__ void k_prep(const float* __restrict__ bn1g, const float* __restrict__ bn1b,
                       const float* __restrict__ W_ih, const float* __restrict__ W_hh,
                       const float* __restrict__ b_ih, const float* __restrict__ b_hh,
                       const float* __restrict__ W_t,  const float* __restrict__ b_t,
                       const float* __restrict__ a) {
    __shared__ float sc[D_], sf[D_];
    int g = threadIdx.x;  // 512; g = gate*128 + ch
    if (g < D_) {
        float inv = 1.f / (float)NT_;
        float m   = g_bn1sum[g] * inv;
        float var = g_bn1sq[g]  * inv - m*m;
        float rs  = rsqrtf(var + 1e-5f);
        sc[g] = rs * bn1g[g];
        sf[g] = bn1b[g] - m * rs * bn1g[g];
    }
    __syncthreads();
    float b = b_ih[g] + b_hh[g];
    for (int d = 0; d < D_; ++d) {
        float w = W_ih[g*D_ + d];
        b += w * sf[d];
        g_WpT[d*G_ + g] = w * sc[d];      // plain layout
    }
    g_biasP[g] = b;                        // plain layout
    if (g < H_) {
        float w1 = 0.f, w2 = 0.f;
        for (int h = 0; h < H_; ++h) { float wt = W_t[h*H_ + g]; w1 += wt*a[h]; w2 += wt*a[H_+h]; }
        g_wa1[g] = w1; g_wa2[g] = w2;
    }
    if (g == 0) {
        float c1 = 0.f, c2 = 0.f;
        for (int h = 0; h < H_; ++h) { c1 += b_t[h]*a[h]; c2 += b_t[h]*a[H_+h]; }
        g_cc[0] = c1; g_cc[1] = c2;
    }
}

// Pack W = [W_hh ; W'] into m16n8k16 B fragments with gate-pair column perm:
// jt = w*8 + 2p + hg, col c: ch = w*16 + p*4 + (c>>1), gate = hg*2 + (c&1).
__global__ void k_packW(const float* __restrict__ W_hh) {
    int idx = blockIdx.x*blockDim.x + threadIdx.x;
    if (idx >= WFRAGN) return;
    int lane = idx & 31;
    int kt = (idx >> 5) % NKT;
    int jt = idx / (NKT*32);
    int w8 = jt >> 3, r = jt & 7, p = r >> 1, hg = r & 1, c = lane >> 2;
    int ch   = w8*16 + p*4 + (c >> 1);
    int gate = hg*2 + (c & 1);
    int grow = gate*H_ + ch;
    int k0 = kt*16 + 2*(lane & 3);
    float w0, w1, w2, w3;
    if (kt < 8) {
        const float* wr = W_hh + (size_t)grow*H_;
        w0 = wr[k0];   w1 = wr[k0+1];
        w2 = wr[k0+8]; w3 = wr[k0+9];
    } else {
        int d0 = k0 - 128;
        w0 = g_WpT[(size_t)d0*G_ + grow];     w1 = g_WpT[(size_t)(d0+1)*G_ + grow];
        w2 = g_WpT[(size_t)(d0+8)*G_ + grow]; w3 = g_WpT[(size_t)(d0+9)*G_ + grow];
    }
    __nv_bfloat16 h0 = __float2bfloat16(w0), h1 = __float2bfloat16(w1);
    __nv_bfloat16 h2 = __float2bfloat16(w2), h3 = __float2bfloat16(w3);
    uint2 vh, vl;
    vh.x = (uint32_t)__bfloat16_as_ushort(h0) | ((uint32_t)__bfloat16_as_ushort(h1) << 16);
    vh.y = (uint32_t)__bfloat16_as_ushort(h2) | ((uint32_t)__bfloat16_as_ushort(h3) << 16);
    vl.x = pack2bf(w0 - __bfloat162float(h0), w1 - __bfloat162float(h1));
    vl.y = pack2bf(w2 - __bfloat162float(h2), w3 - __bfloat162float(h3));
    g_WfragHi[idx] = vh;
    int ntl = jt & 7;
    g_WfragLo2[(((size_t)w8*NKT + kt)*32 + lane)*8 + ntl] = vl;
}

// ---------------- fused persistent tensor LSTM -------------------------------
__global__ void __launch_bounds__(256) k_f() {
    extern __shared__ char smdyn[];
    uint2* Whi = (uint2*)smdyn;
    __shared__ __nv_bfloat16 Ahi[32*ASTR];
    __shared__ __nv_bfloat16 Alo[32*ASTR];
    const int tid  = threadIdx.x, lane = tid & 31, w = tid >> 5;
    const int n0   = blockIdx.x * 32;
    const int t4   = lane & 3;
    const int arow = lane & 15, acolq = (lane >> 4) * 8;
    const int rbase = lane >> 2;
    const int xr_r = tid >> 3, xr_d = (tid & 7) * 8;

    for (int i = tid; i < WFRAGN; i += 256) Whi[i] = g_WfragHi[i];
    for (int i = tid; i < 32*ASTR; i += 256) { Ahi[i] = __float2bfloat16(0.f); Alo[i] = __float2bfloat16(0.f); }

    // channels of this thread: ch(p) = w*16 + p*4 + t4
    float bi[4], bf[4], bg[4], bo[4];
    int chv[4];
    #pragma unroll
    for (int p = 0; p < 4; ++p) {
        int ch = w*16 + p*4 + t4;
        chv[p] = ch;
        bi[p] = g_biasP[ch];
        bf[p] = g_biasP[128 + ch];
        bg[p] = g_biasP[256 + ch];
        bo[p] = g_biasP[384 + ch];
    }
    float cr[2][4][2];
    #pragma unroll
    for (int mt = 0; mt < 2; ++mt)
        #pragma unroll
        for (int p = 0; p < 4; ++p) { cr[mt][p][0] = 0.f; cr[mt][p][1] = 0.f; }

    const uint32_t aHiU = smem_u32(Ahi), aLoU = smem_u32(Alo);

    #define CNV(src0, src1, outh, outl) { \
        __nv_bfloat16 h0c = __float2bfloat16(src0); __nv_bfloat16 h1c = __float2bfloat16(src1); \
        outh = (uint32_t)__bfloat16_as_ushort(h0c) | ((uint32_t)__bfloat16_as_ushort(h1c) << 16); \
        outl = pack2bf(src0 - __bfloat162float(h0c), src1 - __bfloat162float(h1c)); }

    {   // prologue: x(0)
        const float* xs = g_xT + (size_t)n0*D_;
        float4 xa = *(const float4*)&xs[xr_r*64 + xr_d];
        float4 xb = *(const float4*)&xs[xr_r*64 + xr_d + 4];
        uint4 vh, vl;
        CNV(xa.x, xa.y, vh.x, vl.x); CNV(xa.z, xa.w, vh.y, vl.y);
        CNV(xb.x, xb.y, vh.z, vl.z); CNV(xb.z, xb.w, vh.w, vl.w);
        *(uint4*)&Ahi[xr_r*ASTR + 128 + xr_d] = vh;
        *(uint4*)&Alo[xr_r*ASTR + 128 + xr_d] = vl;
    }
    __syncthreads();

    for (int step = 0; step < T_; ++step) {
        float acc[2][8][4];
        #pragma unroll
        for (int mt = 0; mt < 2; ++mt)
            #pragma unroll
            for (int nt = 0; nt < 8; ++nt)
                #pragma unroll
                for (int q = 0; q < 4; ++q) acc[mt][nt][q] = 0.f;

        #pragma unroll 2
        for (int kt = 0; kt < NKT; ++kt) {
            uint32_t ah[2][4], al[2][4];
            #pragma unroll
            for (int mt = 0; mt < 2; ++mt) {
                uint32_t off = (uint32_t)((mt*16 + arow)*ASTR + kt*16 + acolq) * 2u;
                ldsm_x4(ah[mt], aHiU + off);
                ldsm_x4(al[mt], aLoU + off);
            }
            const uint4* p4 = (const uint4*)(g_WfragLo2 + (((size_t)w*NKT + kt)*32 + lane)*8);
            uint4 q0 = p4[0], q1 = p4[1], q2 = p4[2], q3 = p4[3];
            uint2 wl[8] = { {q0.x,q0.y},{q0.z,q0.w},{q1.x,q1.y},{q1.z,q1.w},
                            {q2.x,q2.y},{q2.z,q2.w},{q3.x,q3.y},{q3.z,q3.w} };
            const uint2* whp = Whi + ((size_t)(w*8)*NKT + kt)*32 + lane;
            #pragma unroll
            for (int nt = 0; nt < 8; ++nt) {
                uint2 wh = whp[(size_t)nt * (NKT*32)];
                uint32_t bh[2] = {wh.x, wh.y};
                uint32_t bl[2] = {wl[nt].x, wl[nt].y};
                #pragma unroll
                for (int mt = 0; mt < 2; ++mt) {
                    mma_bf16(acc[mt][nt], ah[mt], bh);
                    mma_bf16(acc[mt][nt], al[mt], bh);
                    mma_bf16(acc[mt][nt], ah[mt], bl);
                }
            }
        }

        float4 xr0, xr1;
        const bool hasx = (step + 1 < T_);
        if (hasx) {
            const float* xs = g_xT + (size_t)(step+1)*N_*D_ + (size_t)n0*D_;
            xr0 = *(const float4*)&xs[xr_r*64 + xr_d];
            xr1 = *(const float4*)&xs[xr_r*64 + xr_d + 4];
        }
        __syncthreads();

        // shuffle-free epilogue: acc[mt][2p] = (i,f) rows r,r+8; acc[mt][2p+1] = (g,o)
        #pragma unroll
        for (int p = 0; p < 4; ++p) {
            int ch = chv[p];
            #pragma unroll
            for (int mt = 0; mt < 2; ++mt) {
                #pragma unroll
                for (int hrow = 0; hrow < 2; ++hrow) {
                    int rloc = rbase + hrow*8 + mt*16;
                    float iv = fsig (acc[mt][2*p  ][2*hrow    ] + bi[p]);
                    float fv = fsig (acc[mt][2*p  ][2*hrow + 1] + bf[p]);
                    float gv = ftanh(acc[mt][2*p+1][2*hrow    ] + bg[p]);
                    float ov = fsig (acc[mt][2*p+1][2*hrow + 1] + bo[p]);
                    float cn = fv * cr[mt][p][hrow] + iv * gv;
                    cr[mt][p][hrow] = cn;
                    float hv = ov * ftanh(cn);
                    __nv_bfloat16 hh = __float2bfloat16(hv);
                    Ahi[rloc*ASTR + ch] = hh;
                    Alo[rloc*ASTR + ch] = __float2bfloat16(hv - __bfloat162float(hh));
                    if (step == T_-1) g_h[(size_t)(n0 + rloc)*H_ + ch] = hv;
                }
            }
        }
        if (hasx) {
            uint4 vh, vl;
            CNV(xr0.x, xr0.y, vh.x, vl.x); CNV(xr0.z, xr0.w, vh.y, vl.y);
            CNV(xr1.x, xr1.y, vh.z, vl.z); CNV(xr1.z, xr1.w, vh.w, vl.w);
            *(uint4*)&Ahi[xr_r*ASTR + 128 + xr_d] = vh;
            *(uint4*)&Alo[xr_r*ASTR + 128 + xr_d] = vl;
        }
        __syncthreads();
    }
    #undef CNV
}

__global__ void k_bn2s() {
    int ch = threadIdx.x;
    int n0 = blockIdx.x * 32;
    float s = 0.f, q = 0.f;
    for (int r = 0; r < 32; ++r) { float v = g_h[(size_t)(n0+r)*H_ + ch]; s += v; q += v*v; }
    atomicAdd(&g_bn2sum[ch], s);
    atomicAdd(&g_bn2sq[ch],  q);
}

__global__ void k_bn2a(const float* __restrict__ g2, const float* __restrict__ b2) {
    int n = blockIdx.x, ch = threadIdx.x;
    float inv = 1.f / (float)N_;
    float m   = g_bn2sum[ch] * inv;
    float var = g_bn2sq[ch]  * inv - m*m;
    float hb  = (g_h[(size_t)n*H_ + ch] - m) * rsqrtf(var + 1e-5f) * g2[ch] + b2[ch];
    g_hb[(size_t)n*H_ + ch] = hb;
    __shared__ float r1[H_], r2[H_];
    r1[ch] = hb * g_wa1[ch];
    r2[ch] = hb * g_wa2[ch];
    __syncthreads();
    for (int s = 64; s > 0; s >>= 1) {
        if (ch < s) { r1[ch] += r1[ch+s]; r2[ch] += r2[ch+s]; }
        __syncthreads();
    }
    if (ch == 0) { g_s1[n] = r1[0] + g_cc[0]; g_s2[n] = r2[0] + g_cc[1]; }
}

// exact rank (descending, ties by index) -> sorted scatter; replaces bitonic
__global__ void k_rank() {
    __shared__ float sv[N_];
    int tid = threadIdx.x;
    for (int i = tid; i < N_; i += 128) sv[i] = g_s1[i];
    __syncthreads();
    int i = blockIdx.x*128 + tid;
    float val = sv[i];
    int rank = 0;
    #pragma unroll 8
    for (int j = 0; j < N_; ++j) {
        float o = sv[j];
        rank += (o > val) || (o == val && j < i);
    }
    g_s1s[rank] = val;
    g_perm[rank] = i;
}

__global__ void k_exp() {
    int i = blockIdx.x*blockDim.x + threadIdx.x;
    float M = g_s1s[0];
    if (i == 0) g_M = M;
    if (i < N_) {
        g_e1[i] = expf(g_s1s[i] - M);
        g_e2[i] = expf(0.01f * g_s1s[i]);
    }
}

__global__ void k_prefix_ch() {
    int ch  = blockIdx.x;
    int tid = threadIdx.x;   // 256
    __shared__ double tsum[256];
    int base = tid * 16;
    {
        double loc[16]; double s = 0.0;
        #pragma unroll
        for (int i = 0; i < 16; ++i) {
            int j = base + i;
            s += (double)g_e1[j] * (double)g_hb[(size_t)g_perm[j]*H_ + ch];
            loc[i] = s;
        }
        tsum[tid] = s; __syncthreads();
        for (int off = 1; off < 256; off <<= 1) {
            double vv = (tid >= off) ? tsum[tid-off] : 0.0;
            __syncthreads();
            tsum[tid] += vv;
            __syncthreads();
        }
        double excl = tsum[tid] - s;
        if (tid == 0) g_P1[ch] = 0.0;
        #pragma unroll
        for (int i = 0; i < 16; ++i) g_P1[(size_t)(base+i+1)*H_ + ch] = excl + loc[i];
    }
    __syncthreads();
    {
        double loc[16]; double s = 0.0;
        #pragma unroll
        for (int i = 0; i < 16; ++i) {
            int j = base + i;
            s += (double)g_e2[j] * (double)g_hb[(size_t)g_perm[j]*H_ + ch];
            loc[i] = s;
        }
        tsum[tid] = s; __syncthreads();
        for (int off = 1; off < 256; off <<= 1) {
            double vv = (tid >= off) ? tsum[tid-off] : 0.0;
            __syncthreads();
            tsum[tid] += vv;
            __syncthreads();
        }
        double excl = tsum[tid] - s;
        if (tid == 0) g_P2[ch] = 0.0;
        #pragma unroll
        for (int i = 0; i < 16; ++i) g_P2[(size_t)(base+i+1)*H_ + ch] = excl + loc[i];
    }
}

__global__ void k_prefix_scalar() {
    int tid = threadIdx.x;   // 256
    __shared__ double tsum[256];
    int base = tid * 16;
    for (int pass = 0; pass < 2; ++pass) {
        const float* e = pass ? g_e2 : g_e1;
        double* P = pass ? g_D2 : g_D1;
        double loc[16]; double s = 0.0;
        #pragma unroll
        for (int i = 0; i < 16; ++i) { s += (double)e[base+i]; loc[i] = s; }
        tsum[tid] = s; __syncthreads();
        for (int off = 1; off < 256; off <<= 1) {
            double vv = (tid >= off) ? tsum[tid-off] : 0.0;
            __syncthreads();
            tsum[tid] += vv;
            __syncthreads();
        }
        double excl = tsum[tid] - s;
        if (tid == 0) P[0] = 0.0;
        #pragma unroll
        for (int i = 0; i < 16; ++i) P[base+i+1] = excl + loc[i];
        __syncthreads();
    }
}

__global__ void __launch_bounds__(256) k_att2(float* __restrict__ out,
                      const float* __restrict__ Wfc, const float* __restrict__ bfc,
                      const float* __restrict__ Wout, const float* __restrict__ bout) {
    extern __shared__ float sfc[];     // [128][129]
    __shared__ float h2s[2][H_];
    __shared__ float redw[8];
    __shared__ int   ksh[2];
    __shared__ float wout_s[H_], bfc_s[H_];
    int tid = threadIdx.x;
    int half = tid >> 7, oc = tid & 127;
    for (int i = tid; i < H_*H_; i += 256) {
        int r = i >> 7, c = i & 127;
        sfc[r*129 + c] = Wfc[i];
    }
    if (tid < H_) { wout_s[tid] = Wout[tid]; bfc_s[tid] = bfc[tid]; }
    __syncthreads();
    float bM = g_M;
    double D2N = g_D2[N_];
    float bout0 = bout[0];
    for (int rp = 0; rp < 16; ++rp) {
        int i = blockIdx.x*32 + rp*2 + half;
        float s2i = g_s2[i];
        if (oc == 0) {
            float thr = -s2i;
            int lo = 0, hi = N_;
            while (lo < hi) { int mid = (lo+hi) >> 1; if (g_s1s[mid] >= thr) lo = mid+1; else hi = mid; }
            ksh[half] = lo;
        }
        __syncthreads();
        int k = ksh[half];
        double f1 = exp((double)s2i + (double)bM);
        double f2 = exp(0.01 * (double)s2i);
        double den = f1 * g_D1[k] + f2 * (D2N - g_D2[k]);
        double num = f1 * g_P1[(size_t)k*H_ + oc]
                   + f2 * (g_P2[(size_t)N_*H_ + oc] - g_P2[(size_t)k*H_ + oc]);
        h2s[half][oc] = (float)(num / den) + g_hb[(size_t)i*H_ + oc];
        __syncthreads();
        float acc = bfc_s[oc];
        #pragma unroll 8
        for (int ch = 0; ch < H_; ++ch) acc += sfc[oc*129 + ch] * h2s[half][ch];
        float h3 = acc >= 0.f ? acc : 0.01f * acc;
        float v = h3 * wout_s[oc];
        #pragma unroll
        for (int o = 16; o > 0; o >>= 1) v += __shfl_down_sync(0xFFFFFFFFu, v, o);
        if ((tid & 31) == 0) redw[tid >> 5] = v;
        __syncthreads();
        if (oc == 0) {
            float tot = redw[half*4] + redw[half*4+1] + redw[half*4+2] + redw[half*4+3];
            out[i] = sigmoidf_(tot + bout0);
        }
        __syncthreads();
    }
}

extern "C" void kernel_launch(void* const* d_in, const int* in_sizes, int n_in,
                              void* d_out, int out_size) {
    const float* x     = (const float*)d_in[0];
    const float* bn1g  = (const float*)d_in[1];
    const float* bn1b  = (const float*)d_in[2];
    const float* W_ih  = (const float*)d_in[3];
    const float* W_hh  = (const float*)d_in[4];
    const float* b_ih  = (const float*)d_in[5];
    const float* b_hh  = (const float*)d_in[6];
    const float* bn2g  = (const float*)d_in[7];
    const float* bn2b  = (const float*)d_in[8];
    const float* W_t   = (const float*)d_in[9];
    const float* b_t   = (const float*)d_in[10];
    const float* a     = (const float*)d_in[11];
    const float* W_fc  = (const float*)d_in[12];
    const float* b_fc  = (const float*)d_in[13];
    const float* W_out = (const float*)d_in[14];
    const float* b_out = (const float*)d_in[15];
    float* out = (float*)d_out;

    const int wsmem   = WFRAGN * (int)sizeof(uint2);    // 196608 B
    const int attsmem = 128 * 129 * (int)sizeof(float); // 66048 B
    cudaFuncSetAttribute(k_f,    cudaFuncAttributeMaxDynamicSharedMemorySize, wsmem);
    cudaFuncSetAttribute(k_att2, cudaFuncAttributeMaxDynamicSharedMemorySize, attsmem);

    k_init<<<1, 256>>>();
    k_xt<<<N_, 256>>>(x);
    k_prep<<<1, 512>>>(bn1g, bn1b, W_ih, W_hh, b_ih, b_hh, W_t, b_t, a);
    k_packW<<<(WFRAGN + 255)/256, 256>>>(W_hh);
    k_f<<<N_/32, 256, wsmem>>>();
    k_bn2s<<<N_/32, 128>>>();
    k_bn2a<<<N_, 128>>>(bn2g, bn2b);
    k_rank<<<N_/128, 128>>>();
    k_exp<<<(N_+255)/256, 256>>>();
    k_prefix_ch<<<H_, 256>>>();
    k_prefix_scalar<<<1, 256>>>();
    k_att2<<<N_/32, 256, attsmem>>>(out, W_fc, b_fc, W_out, b_out);
}

// round 16
// speedup vs baseline: 1.4227x; 1.4227x over previous
#include <cuda_runtime.h>
#include <cuda_bf16.h>
#include <cstdint>
#include <math.h>

#define N_  4096
#define D_  64
#define T_  60
#define H_  128
#define G_  512
#define NT_ 245760
#define KCAT 192
#define NKT 12          // KCAT/16
#define ASTR 200        // A tile bf16 row stride (192 + 8 pad)
#define WFRAGN (64*NKT*32)

// gate dimension stored INTERLEAVED: jcol = ch*4 + gate (0=i,1=f,2=g,3=o).
// LSTM: row-partitioned persistent kernel; input GEMM fused via concatenated K.
// W-hi cached in smem; W-lo streamed (nt-innermost layout, LDG.128).

__device__ float g_xT[(size_t)T_*N_*D_];
__device__ float g_h[N_*H_];
__device__ float g_hb[N_*H_];
__device__ float g_WpT[D_*G_];
__device__ float g_biasP[G_];
__device__ uint2 g_WfragHi[WFRAGN];          // [jt][kt][lane]
__device__ uint2 g_WfragLo2[WFRAGN];         // [w][kt][lane][nt]  (nt innermost)
__device__ float g_bn1sum[D_], g_bn1sq[D_];
__device__ float g_bn2sum[H_], g_bn2sq[H_];
__device__ float g_wa1[H_], g_wa2[H_], g_cc[2];
__device__ float g_s1[N_], g_s2[N_];
__device__ float g_s1s[N_];
__device__ int   g_perm[N_];
__device__ float g_e1[N_], g_e2[N_];
__device__ double g_P1[(size_t)(N_+1)*H_];
__device__ double g_P2[(size_t)(N_+1)*H_];
__device__ double g_D1[N_+1], g_D2[N_+1];
__device__ float g_M;

__device__ __forceinline__ float sigmoidf_(float v) { return 1.f/(1.f + expf(-v)); }
__device__ __forceinline__ float fsig(float x) { return 1.f/(1.f + __expf(-x)); }
__device__ __forceinline__ float ftanh(float x) {
    float e = __expf(-2.f*fabsf(x));
    float r = (1.f - e)/(1.f + e);
    return x < 0.f ? -r : r;
}

__device__ __forceinline__ uint32_t smem_u32(const void* p) {
    uint32_t a;
    asm("{ .reg .u64 t; cvta.to.shared.u64 t, %1; cvt.u32.u64 %0, t; }" : "=r"(a) : "l"(p));
    return a;
}
__device__ __forceinline__ void ldsm_x4(uint32_t* r, uint32_t a) {
    asm volatile("ldmatrix.sync.aligned.m8n8.x4.shared.b16 {%0,%1,%2,%3}, [%4];"
        : "=r"(r[0]), "=r"(r[1]), "=r"(r[2]), "=r"(r[3]) : "r"(a));
}
__device__ __forceinline__ void mma_bf16(float* d, const uint32_t* a, const uint32_t* b) {
    asm volatile("mma.sync.aligned.m16n8k16.row.col.f32.bf16.bf16.f32 "
        "{%0,%1,%2,%3}, {%4,%5,%6,%7}, {%8,%9}, {%0,%1,%2,%3};"
        : "+f"(d[0]), "+f"(d[1]), "+f"(d[2]), "+f"(d[3])
        : "r"(a[0]), "r"(a[1]), "r"(a[2]), "r"(a[3]), "r"(b[0]), "r"(b[1]));
}
__device__ __forceinline__ uint32_t pack2bf(float a, float b) {
    __nv_bfloat16 ha = __float2bfloat16(a), hb = __float2bfloat16(b);
    return (uint32_t)__bfloat16_as_ushort(ha) | ((uint32_t)__bfloat16_as_ushort(hb) << 16);
}

__global__ void k_init() {
    int idx = blockIdx.x*blockDim.x + threadIdx.x;
    if (idx < D_) { g_bn1sum[idx] = 0.f; g_bn1sq[idx] = 0.f; }
    if (idx < H_) { g_bn2sum[idx] = 0.f; g_bn2sq[idx] = 0.f; }
}

// Transpose x [n][d][t] -> g_xT [t][n][d]  +  BN1 stats fused (single x pass)
__global__ void k_xt(const float* __restrict__ x) {
    __shared__ float tile[D_*T_];
    int n = blockIdx.x;
    const float* xp = x + (size_t)n*D_*T_;
    for (int i = threadIdx.x; i < D_*T_; i += 256) tile[i] = xp[i];
    __syncthreads();
    for (int i = threadIdx.x; i < D_*T_; i += 256) {
        int t = i >> 6, d = i & 63;
        g_xT[(size_t)t*N_*D_ + (size_t)n*D_ + d] = tile[d*T_ + t];
    }
    if (threadIdx.x < D_) {
        float s = 0.f, q = 0.f;
        const float* row = tile + threadIdx.x*T_;
        #pragma unroll
        for (int t = 0; t < T_; ++t) { float v = row[t]; s += v; q += v*v; }
        atomicAdd(&g_bn1sum[threadIdx.x], s);
        atomicAdd(&g_bn1sq[threadIdx.x],  q);
    }
}

__global__ void k_prep(const float* __restrict__ bn1g, const float* __restrict__ bn1b,
                       const float* __restrict__ W_ih, const float* __restrict__ W_hh,
                       const float* __restrict__ b_ih, const float* __restrict__ b_hh,
                       const float* __restrict__ W_t,  const float* __restrict__ b_t,
                       const float* __restrict__ a) {
    __shared__ float sc[D_], sf[D_];
    int g = threadIdx.x;  // 512 threads; g = gate*128 + ch (original layout)
    if (g < D_) {
        float inv = 1.f / (float)NT_;
        float m   = g_bn1sum[g] * inv;
        float var = g_bn1sq[g]  * inv - m*m;
        float rs  = rsqrtf(var + 1e-5f);
        sc[g] = rs * bn1g[g];
        sf[g] = bn1b[g] - m * rs * bn1g[g];
    }
    __syncthreads();
    int jcol = (g & 127) * 4 + (g >> 7);
    float b = b_ih[g] + b_hh[g];
    for (int d = 0; d < D_; ++d) {
        float w = W_ih[g*D_ + d];
        b += w * sf[d];
        g_WpT[d*G_ + jcol] = w * sc[d];
    }
    g_biasP[jcol] = b;
    if (g < H_) {
        float w1 = 0.f, w2 = 0.f;
        for (int h = 0; h < H_; ++h) { float wt = W_t[h*H_ + g]; w1 += wt*a[h]; w2 += wt*a[H_+h]; }
        g_wa1[g] = w1; g_wa2[g] = w2;
    }
    if (g == 0) {
        float c1 = 0.f, c2 = 0.f;
        for (int h = 0; h < H_; ++h) { c1 += b_t[h]*a[h]; c2 += b_t[h]*a[H_+h]; }
        g_cc[0] = c1; g_cc[1] = c2;
    }
}

// Pack concatenated W = [W_hh (k 0..127) ; W' (k 128..191)] into m16n8k16
// B fragments. Hi: [jt][kt][lane]; Lo: nt-innermost for LDG.128 streaming.
__global__ void k_packW(const float* __restrict__ W_hh) {
    int idx = blockIdx.x*blockDim.x + threadIdx.x;
    if (idx >= WFRAGN) return;
    int lane = idx & 31;
    int kt = (idx >> 5) % NKT;
    int jt = idx / (NKT*32);
    int j = jt*8 + (lane >> 2);
    int k0 = kt*16 + 2*(lane & 3);
    float w0, w1, w2, w3;
    if (kt < 8) {
        int gate = j & 3, ch = j >> 2;
        const float* wr = W_hh + (size_t)(gate*H_ + ch)*H_;
        w0 = wr[k0];   w1 = wr[k0+1];
        w2 = wr[k0+8]; w3 = wr[k0+9];
    } else {
        int d0 = k0 - 128;
        w0 = g_WpT[(size_t)d0*G_ + j];     w1 = g_WpT[(size_t)(d0+1)*G_ + j];
        w2 = g_WpT[(size_t)(d0+8)*G_ + j]; w3 = g_WpT[(size_t)(d0+9)*G_ + j];
    }
    __nv_bfloat16 h0 = __float2bfloat16(w0), h1 = __float2bfloat16(w1);
    __nv_bfloat16 h2 = __float2bfloat16(w2), h3 = __float2bfloat16(w3);
    uint2 vh, vl;
    vh.x = (uint32_t)__bfloat16_as_ushort(h0) | ((uint32_t)__bfloat16_as_ushort(h1) << 16);
    vh.y = (uint32_t)__bfloat16_as_ushort(h2) | ((uint32_t)__bfloat16_as_ushort(h3) << 16);
    vl.x = pack2bf(w0 - __bfloat162float(h0), w1 - __bfloat162float(h1));
    vl.y = pack2bf(w2 - __bfloat162float(h2), w3 - __bfloat162float(h3));
    g_WfragHi[idx] = vh;
    int w8 = jt >> 3, ntl = jt & 7;
    g_WfragLo2[(((size_t)w8*NKT + kt)*32 + lane)*8 + ntl] = vl;
}

// ---------------- fused persistent tensor LSTM (input GEMM + recurrence) ----
// 128 CTAs x 256 thr. CTA owns 32 rows x ALL 512 jcols. W-hi in smem, W-lo
// streamed (LDG.128). x(t+1) prefetched into regs during MMA. 2 syncs/step.
__global__ void __launch_bounds__(256) k_f() {
    extern __shared__ char smdyn[];
    uint2* Whi = (uint2*)smdyn;
    __shared__ __nv_bfloat16 Ahi[32*ASTR];
    __shared__ __nv_bfloat16 Alo[32*ASTR];
    const int tid  = threadIdx.x, lane = tid & 31, w = tid >> 5;
    const int n0   = blockIdx.x * 32;
    const int g    = lane >> 2, t4 = lane & 3;
    const int arow = lane & 15, acolq = (lane >> 4) * 8;
    const bool oddt = (t4 & 1);
    const int row  = g + (oddt ? 8 : 0);
    const int xr_r = tid >> 3, xr_d = (tid & 7) * 8;

    for (int i = tid; i < WFRAGN; i += 256) Whi[i] = g_WfragHi[i];
    for (int i = tid; i < 32*ASTR; i += 256) { Ahi[i] = __float2bfloat16(0.f); Alo[i] = __float2bfloat16(0.f); }

    float4 bias_v[8];
    #pragma unroll
    for (int nt = 0; nt < 8; ++nt) {
        int ch = (w*8 + nt)*2 + (t4 >> 1);
        bias_v[nt] = *(const float4*)&g_biasP[ch*4];
    }
    float cr[2][8];
    #pragma unroll
    for (int mt = 0; mt < 2; ++mt)
        #pragma unroll
        for (int nt = 0; nt < 8; ++nt) cr[mt][nt] = 0.f;

    const uint32_t aHiU = smem_u32(Ahi), aLoU = smem_u32(Alo);

    {
        const float* xs = g_xT + (size_t)n0*D_;
        float4 xa = *(const float4*)&xs[xr_r*64 + xr_d];
        float4 xb = *(const float4*)&xs[xr_r*64 + xr_d + 4];
        uint4 vh, vl;
        __nv_bfloat16 h0;
        #define CNV(src0, src1, outh, outl) { \
            h0 = __float2bfloat16(src0); __nv_bfloat16 h1b = __float2bfloat16(src1); \
            outh = (uint32_t)__bfloat16_as_ushort(h0) | ((uint32_t)__bfloat16_as_ushort(h1b) << 16); \
            outl = pack2bf(src0 - __bfloat162float(h0), src1 - __bfloat162float(h1b)); }
        CNV(xa.x, xa.y, vh.x, vl.x); CNV(xa.z, xa.w, vh.y, vl.y);
        CNV(xb.x, xb.y, vh.z, vl.z); CNV(xb.z, xb.w, vh.w, vl.w);
        *(uint4*)&Ahi[xr_r*ASTR + 128 + xr_d] = vh;
        *(uint4*)&Alo[xr_r*ASTR + 128 + xr_d] = vl;
    }
    __syncthreads();

    for (int step = 0; step < T_; ++step) {
        float acc[2][8][4];
        #pragma unroll
        for (int mt = 0; mt < 2; ++mt)
            #pragma unroll
            for (int nt = 0; nt < 8; ++nt)
                #pragma unroll
                for (int q = 0; q < 4; ++q) acc[mt][nt][q] = 0.f;

        #pragma unroll 2
        for (int kt = 0; kt < NKT; ++kt) {
            uint32_t ah[2][4], al[2][4];
            #pragma unroll
            for (int mt = 0; mt < 2; ++mt) {
                uint32_t off = (uint32_t)((mt*16 + arow)*ASTR + kt*16 + acolq) * 2u;
                ldsm_x4(ah[mt], aHiU + off);
                ldsm_x4(al[mt], aLoU + off);
            }
            const uint4* p4 = (const uint4*)(g_WfragLo2 + (((size_t)w*NKT + kt)*32 + lane)*8);
            uint4 q0 = p4[0], q1 = p4[1], q2 = p4[2], q3 = p4[3];
            uint2 wl[8] = { {q0.x,q0.y},{q0.z,q0.w},{q1.x,q1.y},{q1.z,q1.w},
                            {q2.x,q2.y},{q2.z,q2.w},{q3.x,q3.y},{q3.z,q3.w} };
            const uint2* whp = Whi + ((size_t)(w*8)*NKT + kt)*32 + lane;
            #pragma unroll
            for (int nt = 0; nt < 8; ++nt) {
                uint2 wh = whp[(size_t)nt * (NKT*32)];
                uint32_t bh[2] = {wh.x, wh.y};
                uint32_t bl[2] = {wl[nt].x, wl[nt].y};
                #pragma unroll
                for (int mt = 0; mt < 2; ++mt) {
                    mma_bf16(acc[mt][nt], ah[mt], bh);
                    mma_bf16(acc[mt][nt], al[mt], bh);
                    mma_bf16(acc[mt][nt], ah[mt], bl);
                }
            }
        }

        float4 xr0, xr1;
        const bool hasx = (step + 1 < T_);
        if (hasx) {
            const float* xs = g_xT + (size_t)(step+1)*N_*D_ + (size_t)n0*D_;
            xr0 = *(const float4*)&xs[xr_r*64 + xr_d];
            xr1 = *(const float4*)&xs[xr_r*64 + xr_d + 4];
        }
        __syncthreads();

        #pragma unroll
        for (int nt = 0; nt < 8; ++nt) {
            int ch = (w*8 + nt)*2 + (t4 >> 1);
            float4 xb = bias_v[nt];
            #pragma unroll
            for (int mt = 0; mt < 2; ++mt) {
                float p0 = __shfl_xor_sync(0xFFFFFFFFu, acc[mt][nt][0], 1);
                float p1 = __shfl_xor_sync(0xFFFFFFFFu, acc[mt][nt][1], 1);
                float p2 = __shfl_xor_sync(0xFFFFFFFFu, acc[mt][nt][2], 1);
                float p3 = __shfl_xor_sync(0xFFFFFFFFu, acc[mt][nt][3], 1);
                int rloc = row + mt*16;
                float iv, fv, gv, ov;
                if (!oddt) { iv = acc[mt][nt][0]; fv = acc[mt][nt][1]; gv = p0;             ov = p1;             }
                else       { iv = p2;             fv = p3;             gv = acc[mt][nt][2]; ov = acc[mt][nt][3]; }
                iv = fsig (iv + xb.x);
                fv = fsig (fv + xb.y);
                gv = ftanh(gv + xb.z);
                ov = fsig (ov + xb.w);
                float cn = fv * cr[mt][nt] + iv * gv;
                cr[mt][nt] = cn;
                float hv = ov * ftanh(cn);
                __nv_bfloat16 hh = __float2bfloat16(hv);
                Ahi[rloc*ASTR + ch] = hh;
                Alo[rloc*ASTR + ch] = __float2bfloat16(hv - __bfloat162float(hh));
                if (step == T_-1) g_h[(size_t)(n0 + rloc)*H_ + ch] = hv;
            }
        }
        if (hasx) {
            uint4 vh, vl;
            __nv_bfloat16 h0;
            CNV(xr0.x, xr0.y, vh.x, vl.x); CNV(xr0.z, xr0.w, vh.y, vl.y);
            CNV(xr1.x, xr1.y, vh.z, vl.z); CNV(xr1.z, xr1.w, vh.w, vl.w);
            *(uint4*)&Ahi[xr_r*ASTR + 128 + xr_d] = vh;
            *(uint4*)&Alo[xr_r*ASTR + 128 + xr_d] = vl;
        }
        __syncthreads();
    }
    #undef CNV
}

__global__ void k_bn2s() {
    int ch = threadIdx.x;
    int n0 = blockIdx.x * 32;
    float s = 0.f, q = 0.f;
    for (int r = 0; r < 32; ++r) { float v = g_h[(size_t)(n0+r)*H_ + ch]; s += v; q += v*v; }
    atomicAdd(&g_bn2sum[ch], s);
    atomicAdd(&g_bn2sq[ch],  q);
}

__global__ void k_bn2a(const float* __restrict__ g2, const float* __restrict__ b2) {
    int n = blockIdx.x, ch = threadIdx.x;
    float inv = 1.f / (float)N_;
    float m   = g_bn2sum[ch] * inv;
    float var = g_bn2sq[ch]  * inv - m*m;
    float hb  = (g_h[(size_t)n*H_ + ch] - m) * rsqrtf(var + 1e-5f) * g2[ch] + b2[ch];
    g_hb[(size_t)n*H_ + ch] = hb;
    __shared__ float r1[H_], r2[H_];
    r1[ch] = hb * g_wa1[ch];
    r2[ch] = hb * g_wa2[ch];
    __syncthreads();
    for (int s = 64; s > 0; s >>= 1) {
        if (ch < s) { r1[ch] += r1[ch+s]; r2[ch] += r2[ch+s]; }
        __syncthreads();
    }
    if (ch == 0) { g_s1[n] = r1[0] + g_cc[0]; g_s2[n] = r2[0] + g_cc[1]; }
}

// exact rank (descending, ties by index) -> sorted scatter; replaces bitonic
__global__ void k_rank() {
    __shared__ float sv[N_];
    int tid = threadIdx.x;
    for (int i = tid; i < N_; i += 128) sv[i] = g_s1[i];
    __syncthreads();
    int i = blockIdx.x*128 + tid;
    float val = sv[i];
    int rank = 0;
    #pragma unroll 8
    for (int j = 0; j < N_; ++j) {
        float o = sv[j];
        rank += (o > val) || (o == val && j < i);
    }
    g_s1s[rank] = val;
    g_perm[rank] = i;
}

__global__ void k_exp() {
    int i = blockIdx.x*blockDim.x + threadIdx.x;
    float M = g_s1s[0];
    if (i == 0) g_M = M;
    if (i < N_) {
        g_e1[i] = expf(g_s1s[i] - M);
        g_e2[i] = expf(0.01f * g_s1s[i]);
    }
}

__global__ void k_prefix_ch() {
    int ch  = blockIdx.x;
    int tid = threadIdx.x;   // 256
    __shared__ double tsum[256];
    int base = tid * 16;
    {
        double loc[16]; double s = 0.0;
        #pragma unroll
        for (int i = 0; i < 16; ++i) {
            int j = base + i;
            s += (double)g_e1[j] * (double)g_hb[(size_t)g_perm[j]*H_ + ch];
            loc[i] = s;
        }
        tsum[tid] = s; __syncthreads();
        for (int off = 1; off < 256; off <<= 1) {
            double vv = (tid >= off) ? tsum[tid-off] : 0.0;
            __syncthreads();
            tsum[tid] += vv;
            __syncthreads();
        }
        double excl = tsum[tid] - s;
        if (tid == 0) g_P1[0*H_ + ch] = 0.0;
        #pragma unroll
        for (int i = 0; i < 16; ++i) g_P1[(size_t)(base+i+1)*H_ + ch] = excl + loc[i];
    }
    __syncthreads();
    {
        double loc[16]; double s = 0.0;
        #pragma unroll
        for (int i = 0; i < 16; ++i) {
            int j = base + i;
            s += (double)g_e2[j] * (double)g_hb[(size_t)g_perm[j]*H_ + ch];
            loc[i] = s;
        }
        tsum[tid] = s; __syncthreads();
        for (int off = 1; off < 256; off <<= 1) {
            double vv = (tid >= off) ? tsum[tid-off] : 0.0;
            __syncthreads();
            tsum[tid] += vv;
            __syncthreads();
        }
        double excl = tsum[tid] - s;
        if (tid == 0) g_P2[0*H_ + ch] = 0.0;
        #pragma unroll
        for (int i = 0; i < 16; ++i) g_P2[(size_t)(base+i+1)*H_ + ch] = excl + loc[i];
    }
}

__global__ void k_prefix_scalar() {
    int tid = threadIdx.x;   // 256
    __shared__ double tsum[256];
    int base = tid * 16;
    for (int pass = 0; pass < 2; ++pass) {
        const float* e = pass ? g_e2 : g_e1;
        double* P = pass ? g_D2 : g_D1;
        double loc[16]; double s = 0.0;
        #pragma unroll
        for (int i = 0; i < 16; ++i) { s += (double)e[base+i]; loc[i] = s; }
        tsum[tid] = s; __syncthreads();
        for (int off = 1; off < 256; off <<= 1) {
            double vv = (tid >= off) ? tsum[tid-off] : 0.0;
            __syncthreads();
            tsum[tid] += vv;
            __syncthreads();
        }
        double excl = tsum[tid] - s;
        if (tid == 0) P[0] = 0.0;
        #pragma unroll
        for (int i = 0; i < 16; ++i) P[base+i+1] = excl + loc[i];
        __syncthreads();
    }
}

__global__ void __launch_bounds__(256) k_att2(float* __restrict__ out,
                      const float* __restrict__ Wfc, const float* __restrict__ bfc,
                      const float* __restrict__ Wout, const float* __restrict__ bout) {
    extern __shared__ float sfc[];     // [128][129]
    __shared__ float h2s[2][H_];
    __shared__ float redw[8];
    __shared__ int   ksh[2];
    __shared__ float wout_s[H_], bfc_s[H_];
    int tid = threadIdx.x;
    int half = tid >> 7, oc = tid & 127;
    for (int i = tid; i < H_*H_; i += 256) {
        int r = i >> 7, c = i & 127;
        sfc[r*129 + c] = Wfc[i];
    }
    if (tid < H_) { wout_s[tid] = Wout[tid]; bfc_s[tid] = bfc[tid]; }
    __syncthreads();
    float bM = g_M;
    double D2N = g_D2[N_];
    float bout0 = bout[0];
    for (int rp = 0; rp < 16; ++rp) {
        int i = blockIdx.x*32 + rp*2 + half;
        float s2i = g_s2[i];
        if (oc == 0) {
            float thr = -s2i;
            int lo = 0, hi = N_;
            while (lo < hi) { int mid = (lo+hi) >> 1; if (g_s1s[mid] >= thr) lo = mid+1; else hi = mid; }
            ksh[half] = lo;
        }
        __syncthreads();
        int k = ksh[half];
        double f1 = exp((double)s2i + (double)bM);
        double f2 = exp(0.01 * (double)s2i);
        double den = f1 * g_D1[k] + f2 * (D2N - g_D2[k]);
        double num = f1 * g_P1[(size_t)k*H_ + oc]
                   + f2 * (g_P2[(size_t)N_*H_ + oc] - g_P2[(size_t)k*H_ + oc]);
        h2s[half][oc] = (float)(num / den) + g_hb[(size_t)i*H_ + oc];
        __syncthreads();
        float acc = bfc_s[oc];
        #pragma unroll 8
        for (int ch = 0; ch < H_; ++ch) acc += sfc[oc*129 + ch] * h2s[half][ch];
        float h3 = acc >= 0.f ? acc : 0.01f * acc;
        float v = h3 * wout_s[oc];
        #pragma unroll
        for (int o = 16; o > 0; o >>= 1) v += __shfl_down_sync(0xFFFFFFFFu, v, o);
        if ((tid & 31) == 0) redw[tid >> 5] = v;
        __syncthreads();
        if (oc == 0) {
            float tot = redw[half*4] + redw[half*4+1] + redw[half*4+2] + redw[half*4+3];
            out[i] = sigmoidf_(tot + bout0);
        }
        __syncthreads();
    }
}

extern "C" void kernel_launch(void* const* d_in, const int* in_sizes, int n_in,
                              void* d_out, int out_size) {
    const float* x     = (const float*)d_in[0];
    const float* bn1g  = (const float*)d_in[1];
    const float* bn1b  = (const float*)d_in[2];
    const float* W_ih  = (const float*)d_in[3];
    const float* W_hh  = (const float*)d_in[4];
    const float* b_ih  = (const float*)d_in[5];
    const float* b_hh  = (const float*)d_in[6];
    const float* bn2g  = (const float*)d_in[7];
    const float* bn2b  = (const float*)d_in[8];
    const float* W_t   = (const float*)d_in[9];
    const float* b_t   = (const float*)d_in[10];
    const float* a     = (const float*)d_in[11];
    const float* W_fc  = (const float*)d_in[12];
    const float* b_fc  = (const float*)d_in[13];
    const float* W_out = (const float*)d_in[14];
    const float* b_out = (const float*)d_in[15];
    float* out = (float*)d_out;

    const int wsmem   = WFRAGN * (int)sizeof(uint2);    // 196608 B
    const int attsmem = 128 * 129 * (int)sizeof(float); // 66048 B
    cudaFuncSetAttribute(k_f,    cudaFuncAttributeMaxDynamicSharedMemorySize, wsmem);
    cudaFuncSetAttribute(k_att2, cudaFuncAttributeMaxDynamicSharedMemorySize, attsmem);

    k_init<<<1, 256>>>();
    k_xt<<<N_, 256>>>(x);
    k_prep<<<1, 512>>>(bn1g, bn1b, W_ih, W_hh, b_ih, b_hh, W_t, b_t, a);
    k_packW<<<(WFRAGN + 255)/256, 256>>>(W_hh);
    k_f<<<N_/32, 256, wsmem>>>();
    k_bn2s<<<N_/32, 128>>>();
    k_bn2a<<<N_, 128>>>(bn2g, bn2b);
    k_rank<<<N_/128, 128>>>();
    k_exp<<<(N_+255)/256, 256>>>();
    k_prefix_ch<<<H_, 256>>>();
    k_prefix_scalar<<<1, 256>>>();
    k_att2<<<N_/32, 256, attsmem>>>(out, W_fc, b_fc, W_out, b_out);
}